// round 12
// baseline (speedup 1.0000x reference)
#include <cuda_runtime.h>
#include <cstdint>
#include <math.h>
#include <math_constants.h>

// ---------------- problem constants ----------------
#define B_    16
#define Hdim  64
#define Wdim  64
#define C_    512
#define NH_   16
#define WS_   8
#define SS_   4
#define P_    4
#define HID_  2048
#define N_    64            // WS*WS
#define HD_   32            // C/NH
#define NWIN_ 64
#define BW_   1024          // B * NWIN
#define ROWS_ 65536         // B * H * W
#define SCALE_ 0.176776695296636893f   // 32^-0.5

// ---------------- scratch (static device memory; no allocations) ----------------
__device__ float g_hw [(size_t)ROWS_ * C_];           // LN1 + shifted-window partition
__device__ float g_q  [(size_t)BW_ * NH_ * N_ * HD_]; // (bw,h,n,d), pre-scaled
__device__ float g_k  [(size_t)BW_ * NH_ * N_ * HD_];
__device__ float g_v  [(size_t)BW_ * NH_ * N_ * HD_];
__device__ float g_bias[(size_t)BW_ * NH_ * N_ * N_]; // A_phi + A_r + mask
__device__ float g_ao [(size_t)ROWS_ * C_];           // attention output (windowed order)
__device__ float g_x2 [(size_t)ROWS_ * C_];           // shortcut + proj (spatial order)
__device__ float g_ln2[(size_t)ROWS_ * C_];
__device__ float g_mlp[(size_t)ROWS_ * HID_];

// ---------------- helpers ----------------
__device__ __forceinline__ uint32_t to_tf32_u(float x) {
    uint32_t u;
    asm("cvt.rna.tf32.f32 %0, %1;" : "=r"(u) : "f"(x));
    return u;
}
__device__ __forceinline__ float to_tf32_f(float x) {
    return __uint_as_float(to_tf32_u(x));
}

__device__ __forceinline__ void mma_tf32(float* c, const uint32_t* a, const uint32_t* b) {
    asm volatile(
        "mma.sync.aligned.m16n8k8.row.col.f32.tf32.tf32.f32 "
        "{%0,%1,%2,%3}, {%4,%5,%6,%7}, {%8,%9}, {%0,%1,%2,%3};\n"
        : "+f"(c[0]), "+f"(c[1]), "+f"(c[2]), "+f"(c[3])
        : "r"(a[0]), "r"(a[1]), "r"(a[2]), "r"(a[3]),
          "r"(b[0]), "r"(b[1]));
}

__device__ __forceinline__ void cp16(void* smem, const void* gmem) {
    uint32_t s = (uint32_t)__cvta_generic_to_shared(smem);
    asm volatile("cp.async.cg.shared.global [%0], [%1], 16;\n" :: "r"(s), "l"(gmem));
}

// ---------------- LayerNorm (optionally fused with roll + window partition) ----------------
__global__ __launch_bounds__(256) void ln_kernel(
    const float* __restrict__ x, const float* __restrict__ gamma,
    const float* __restrict__ beta, float* __restrict__ out, int win_map)
{
    int row = blockIdx.x;
    int src = row;
    if (win_map) {
        int b   = row >> 12;
        int win = (row >> 6) & 63;
        int n   = row & 63;
        int hh  = (((win >> 3) << 3) + (n >> 3) + SS_) & 63;
        int ww  = (((win & 7) << 3) + (n & 7) + SS_) & 63;
        src = (b << 12) + (hh << 6) + ww;
    }
    int t = threadIdx.x;
    const float2* xr = (const float2*)(x + (size_t)src * C_);
    float2 v = xr[t];
    float s  = v.x + v.y;
    float sq = v.x * v.x + v.y * v.y;
    #pragma unroll
    for (int o = 16; o > 0; o >>= 1) {
        s  += __shfl_xor_sync(0xffffffffu, s,  o);
        sq += __shfl_xor_sync(0xffffffffu, sq, o);
    }
    __shared__ float redS[8], redQ[8], mv[2];
    int w = t >> 5, l = t & 31;
    if (l == 0) { redS[w] = s; redQ[w] = sq; }
    __syncthreads();
    if (t == 0) {
        float ts = 0.f, tq = 0.f;
        #pragma unroll
        for (int i = 0; i < 8; i++) { ts += redS[i]; tq += redQ[i]; }
        float mean = ts * (1.f / 512.f);
        float var  = tq * (1.f / 512.f) - mean * mean;
        mv[0] = mean; mv[1] = rsqrtf(var + 1e-5f);
    }
    __syncthreads();
    float mean = mv[0], r = mv[1];
    float2 gv = ((const float2*)gamma)[t];
    float2 bv = ((const float2*)beta)[t];
    float2 o2;
    o2.x = (v.x - mean) * r * gv.x + bv.x;
    o2.y = (v.y - mean) * r * gv.y + bv.y;
    ((float2*)(out + (size_t)row * C_))[t] = o2;
}

// ---------------- bias: A_phi + A_r + shift mask, for all heads ----------------
__global__ __launch_bounds__(256) void bias_kernel(
    const float* __restrict__ D,
    const float* __restrict__ a_p, const float* __restrict__ b_p,
    const float* __restrict__ a_r, const float* __restrict__ b_r)
{
    int bw = blockIdx.x;      // 0..1023
    int t  = threadIdx.x;
    __shared__ float dws[64];
    __shared__ int   regv[64];
    __shared__ float arS[80], brS[64];
    __shared__ float aphi[15 * 16];   // [delta+7][head]

    int b = bw >> 6, win = bw & 63;
    int wh = win >> 3, wc = win & 7;

    if (t < 64) {
        int r = t >> 3, sc = t & 7;
        int hh  = ((wh << 3) + r + SS_) & 63;
        int wcc = ((wc << 3) + sc + SS_) & 63;
        dws[t] = D[(b << 12) + (hh << 6) + wcc];
        int h0 = (wh << 3) + r;
        int w0 = (wc << 3) + sc;
        int rh = (h0 < 56) ? 0 : (h0 < 60 ? 1 : 2);
        int rw = (w0 < 56) ? 0 : (w0 < 60 ? 1 : 2);
        regv[t] = rh * 3 + rw;
    }
    for (int i = t; i < 80; i += 256) arS[i] = a_r[i];
    for (int i = t; i < 64; i += 256) brS[i] = b_r[i];
    for (int e = t; e < 240; e += 256) {
        int di = e / 16, hdx = e % 16;
        float th = (float)(di - 7) * (2.0f * CUDART_PI_F / 64.0f);
        float c1, s1; sincosf(th, &s1, &c1);
        float cp = c1, sp = s1, cpm = 1.f, spm = 0.f;
        float acc = a_p[hdx];
        #pragma unroll
        for (int p = 0; p < 4; p++) {
            acc += 0.25f * (cp * a_p[(p + 1) * 16 + hdx] + sp * b_p[p * 16 + hdx]);
            float cn = 2.f * c1 * cp - cpm;
            float sn = 2.f * c1 * sp - spm;
            cpm = cp; spm = sp; cp = cn; sp = sn;
        }
        aphi[e] = acc;
    }
    __syncthreads();

    float* bout = g_bias + (size_t)bw * (NH_ * 4096);
    for (int idx = t; idx < 4096; idx += 256) {
        int n = idx >> 6, m = idx & 63;
        float rad = dws[m] - dws[n];
        float c1, s1; sincosf(rad * CUDART_PI_F, &s1, &c1);
        float c2 = 2.f * c1 * c1 - 1.f;
        float s2 = 2.f * c1 * s1;
        float c3 = 2.f * c1 * c2 - c1;
        float s3 = 2.f * c1 * s2 - s1;
        float c4 = 2.f * c1 * c3 - c2;
        float s4 = 2.f * c1 * s3 - s2;
        float mk = (regv[n] == regv[m]) ? 0.f : -100.f;
        const float* ap_row = &aphi[((n & 7) - (m & 7) + 7) * 16];
        #pragma unroll
        for (int h = 0; h < 16; h++) {
            float val = ap_row[h] + arS[h]
                + 0.25f * (c1 * arS[16 + h] + c2 * arS[32 + h] + c3 * arS[48 + h] + c4 * arS[64 + h]
                         + s1 * brS[h]      + s2 * brS[16 + h] + s3 * brS[32 + h] + s4 * brS[48 + h])
                + mk;
            bout[h * 4096 + idx] = val;
        }
    }
}

// ---------------- tf32 tensor-core GEMM, 128x128 block, 2-stage cp.async (round-6 loop) ----------------
// A staged [m][k] stride 20 (conflict-free), B staged [k][n] stride 132.
// EPI 0: QKV split/scatter (+bias, q pre-scaled)   A=g_hw  B=Wqkv
// EPI 1: proj (+bias) + window-reverse + roll + shortcut -> g_x2
// EPI 2: MLP1 (+bias) + exact GELU -> g_mlp
// EPI 3: MLP2 (+bias) + residual(g_x2) -> d_out
#define APAD 20
#define BPAD 132
template<int EPI>
__global__ __launch_bounds__(256, 2) void sgemm_tc(
    const float* __restrict__ A, const float* __restrict__ Bw,
    const float* __restrict__ bias, const float* __restrict__ resid,
    float* __restrict__ out, int K, int Nn)
{
    __shared__ float As[2][128][APAD];
    __shared__ float Bs[2][16][BPAD];
    int bx = blockIdx.x, by = blockIdx.y;
    int t  = threadIdx.x;
    int warp = t >> 5, lane = t & 31;
    int wm = warp >> 2, wn = warp & 3;     // warps 2(m) x 4(n)
    int m0 = wm * 64, n0 = wn * 32;
    int grp = lane >> 2, t4 = lane & 3;

    float acc[4][4][4];
    #pragma unroll
    for (int i = 0; i < 4; i++)
        #pragma unroll
        for (int j = 0; j < 4; j++)
            #pragma unroll
            for (int r = 0; r < 4; r++) acc[i][j][r] = 0.f;

    const float* Ap = A + (size_t)(by * 128) * K;
    const float* Bp = Bw + bx * 128;

    auto issue = [&](int stage, int k0) {
        #pragma unroll
        for (int i = 0; i < 2; i++) {
            int c2 = t + i * 256;
            int ar = c2 >> 2, ak = (c2 & 3) << 2;       // A: 128 rows x 4 chunks
            cp16(&As[stage][ar][ak], Ap + (size_t)ar * K + k0 + ak);
            int br = c2 >> 5, bc = (c2 & 31) << 2;      // B: 16 rows x 32 chunks
            cp16(&Bs[stage][br][bc], Bp + (size_t)(k0 + br) * Nn + bc);
        }
        asm volatile("cp.async.commit_group;\n");
    };

    int ntiles = K >> 4;
    issue(0, 0);
    for (int it = 0; it < ntiles; it++) {
        int s = it & 1;
        if (it + 1 < ntiles) issue(s ^ 1, (it + 1) << 4);
        asm volatile("cp.async.wait_group 1;\n");
        __syncthreads();
        #pragma unroll
        for (int ks = 0; ks < 16; ks += 8) {
            uint32_t af[4][4], bf[4][2];
            #pragma unroll
            for (int mi = 0; mi < 4; mi++) {
                int mr = m0 + mi * 16;
                af[mi][0] = to_tf32_u(As[s][mr + grp    ][ks + t4    ]);
                af[mi][1] = to_tf32_u(As[s][mr + grp + 8][ks + t4    ]);
                af[mi][2] = to_tf32_u(As[s][mr + grp    ][ks + t4 + 4]);
                af[mi][3] = to_tf32_u(As[s][mr + grp + 8][ks + t4 + 4]);
            }
            #pragma unroll
            for (int ni = 0; ni < 4; ni++) {
                int nc = n0 + ni * 8;
                bf[ni][0] = to_tf32_u(Bs[s][ks + t4    ][nc + grp]);
                bf[ni][1] = to_tf32_u(Bs[s][ks + t4 + 4][nc + grp]);
            }
            #pragma unroll
            for (int mi = 0; mi < 4; mi++)
                #pragma unroll
                for (int ni = 0; ni < 4; ni++)
                    mma_tf32(acc[mi][ni], af[mi], bf[ni]);
        }
        __syncthreads();
    }

    // epilogue: per (mi,ni) thread owns rows {r0, r0+8}, cols {c, c+1}
    int rb = by * 128 + m0;
    int cb = bx * 128 + n0;

    #pragma unroll
    for (int mi = 0; mi < 4; mi++) {
        int r0 = rb + mi * 16 + grp;
        #pragma unroll
        for (int ni = 0; ni < 4; ni++) {
            int c = cb + ni * 8 + 2 * t4;
            float2 bb = *(const float2*)(bias + c);
            float v00 = acc[mi][ni][0] + bb.x;
            float v01 = acc[mi][ni][1] + bb.y;
            float v10 = acc[mi][ni][2] + bb.x;
            float v11 = acc[mi][ni][3] + bb.y;

            if (EPI == 0) {  // QKV scatter
                int s  = c >> 9;
                int hh = (c >> 5) & 15;
                int db = c & 31;
                float* dst = (s == 0) ? g_q : (s == 1 ? g_k : g_v);
                float mul = (s == 0) ? SCALE_ : 1.f;
                #pragma unroll
                for (int h = 0; h < 2; h++) {
                    int row = r0 + h * 8;
                    int bw = row >> 6, n = row & 63;
                    size_t off = ((size_t)(bw * 16 + hh)) * 2048 + n * 32 + db;
                    float2 o2;
                    o2.x = (h ? v10 : v00) * mul;
                    o2.y = (h ? v11 : v01) * mul;
                    *(float2*)(dst + off) = o2;
                }
            } else if (EPI == 1) {  // proj + window-reverse + roll + shortcut
                #pragma unroll
                for (int h = 0; h < 2; h++) {
                    int row = r0 + h * 8;
                    int b = row >> 12, win = (row >> 6) & 63, n = row & 63;
                    int hh = (((win >> 3) << 3) + (n >> 3) + SS_) & 63;
                    int wc = (((win & 7) << 3) + (n & 7) + SS_) & 63;
                    size_t dest = ((size_t)((b << 12) + (hh << 6) + wc)) * 512 + c;
                    float2 rs = *(const float2*)(resid + dest);
                    float2 o2;
                    o2.x = rs.x + (h ? v10 : v00);
                    o2.y = rs.y + (h ? v11 : v01);
                    *(float2*)(g_x2 + dest) = o2;
                }
            } else if (EPI == 2) {  // MLP1 + exact GELU
                #pragma unroll
                for (int h = 0; h < 2; h++) {
                    int row = r0 + h * 8;
                    size_t o = (size_t)row * Nn + c;
                    float a0 = h ? v10 : v00;
                    float a1 = h ? v11 : v01;
                    float2 o2;
                    o2.x = 0.5f * a0 * (1.f + erff(a0 * 0.70710678118654752f));
                    o2.y = 0.5f * a1 * (1.f + erff(a1 * 0.70710678118654752f));
                    *(float2*)(g_mlp + o) = o2;
                }
            } else {  // MLP2 + residual
                #pragma unroll
                for (int h = 0; h < 2; h++) {
                    int row = r0 + h * 8;
                    size_t o = (size_t)row * 512 + c;
                    float2 rs = *(const float2*)(g_x2 + o);
                    float2 o2;
                    o2.x = rs.x + (h ? v10 : v00);
                    o2.y = rs.y + (h ? v11 : v01);
                    *(float2*)(out + o) = o2;
                }
            }
        }
    }
}

// ---------------- attention via tensor cores: one block (128 thr, 4 warps) per (window, head) ----------------
// S = Q K^T + bias; softmax; O = P V.  All mma.sync m16n8k8 tf32.
// Warp w owns rows [w*16, w*16+16). smem strides: 36 (qs/ks), 68 (vt/ps) — all
// fragment LDS patterns map to banks grp*4+t4 (+const) = conflict-free.
__global__ __launch_bounds__(128) void attn_tc()
{
    int bh = blockIdx.x;            // bw*16 + h
    int t  = threadIdx.x;
    int warp = t >> 5, lane = t & 31;
    int grp = lane >> 2, t4 = lane & 3;
    int m0 = warp * 16;

    __shared__ float qs[64 * 36];   // Q (tf32 values)
    __shared__ float ks[64 * 36];   // K (tf32 values)
    __shared__ float vt[32 * 68];   // V^T [d][j] (tf32 values)
    __shared__ float ps[64 * 68];   // bias (fp32), then P (tf32 values)

    const float4* qg = (const float4*)(g_q + (size_t)bh * 2048);
    const float4* kg = (const float4*)(g_k + (size_t)bh * 2048);
    const float4* vg = (const float4*)(g_v + (size_t)bh * 2048);
    for (int i = t; i < 512; i += 128) {
        int n = i >> 3, kk = (i & 7) << 2;
        float4 qv = qg[i];
        float4 kv = kg[i];
        float4 cq, ck;
        cq.x = to_tf32_f(qv.x); cq.y = to_tf32_f(qv.y); cq.z = to_tf32_f(qv.z); cq.w = to_tf32_f(qv.w);
        ck.x = to_tf32_f(kv.x); ck.y = to_tf32_f(kv.y); ck.z = to_tf32_f(kv.z); ck.w = to_tf32_f(kv.w);
        *(float4*)&qs[n * 36 + kk] = cq;
        *(float4*)&ks[n * 36 + kk] = ck;
        float4 vv = vg[i];
        vt[(kk + 0) * 68 + n] = to_tf32_f(vv.x);
        vt[(kk + 1) * 68 + n] = to_tf32_f(vv.y);
        vt[(kk + 2) * 68 + n] = to_tf32_f(vv.z);
        vt[(kk + 3) * 68 + n] = to_tf32_f(vv.w);
    }
    const float4* bgp = (const float4*)(g_bias + (size_t)bh * 4096);
    for (int i = t; i < 1024; i += 128) {
        int n = i >> 4, c4 = (i & 15) << 2;
        *(float4*)&ps[n * 68 + c4] = bgp[i];
    }
    __syncthreads();

    // ---- S = Q K^T : 4 k-tiles x 8 n-tiles of m16n8k8 ----
    float sacc[8][4];
    #pragma unroll
    for (int ni = 0; ni < 8; ni++)
        #pragma unroll
        for (int r = 0; r < 4; r++) sacc[ni][r] = 0.f;

    #pragma unroll
    for (int kk = 0; kk < 32; kk += 8) {
        uint32_t a[4];
        a[0] = __float_as_uint(qs[(m0 + grp    ) * 36 + kk + t4    ]);
        a[1] = __float_as_uint(qs[(m0 + grp + 8) * 36 + kk + t4    ]);
        a[2] = __float_as_uint(qs[(m0 + grp    ) * 36 + kk + t4 + 4]);
        a[3] = __float_as_uint(qs[(m0 + grp + 8) * 36 + kk + t4 + 4]);
        #pragma unroll
        for (int ni = 0; ni < 8; ni++) {
            uint32_t b[2];
            b[0] = __float_as_uint(ks[(ni * 8 + grp) * 36 + kk + t4    ]);
            b[1] = __float_as_uint(ks[(ni * 8 + grp) * 36 + kk + t4 + 4]);
            mma_tf32(sacc[ni], a, b);
        }
    }

    // ---- + bias, softmax over the row (64 cols spread over 4 lanes x 8 ni x 2) ----
    int r0 = m0 + grp, r1 = r0 + 8;
    #pragma unroll
    for (int ni = 0; ni < 8; ni++) {
        int c = ni * 8 + 2 * t4;
        float2 b0 = *(const float2*)&ps[r0 * 68 + c];
        float2 b1 = *(const float2*)&ps[r1 * 68 + c];
        sacc[ni][0] += b0.x; sacc[ni][1] += b0.y;
        sacc[ni][2] += b1.x; sacc[ni][3] += b1.y;
    }
    float mx0 = sacc[0][0], mx1 = sacc[0][2];
    #pragma unroll
    for (int ni = 0; ni < 8; ni++) {
        mx0 = fmaxf(mx0, fmaxf(sacc[ni][0], sacc[ni][1]));
        mx1 = fmaxf(mx1, fmaxf(sacc[ni][2], sacc[ni][3]));
    }
    mx0 = fmaxf(mx0, __shfl_xor_sync(0xffffffffu, mx0, 1));
    mx0 = fmaxf(mx0, __shfl_xor_sync(0xffffffffu, mx0, 2));
    mx1 = fmaxf(mx1, __shfl_xor_sync(0xffffffffu, mx1, 1));
    mx1 = fmaxf(mx1, __shfl_xor_sync(0xffffffffu, mx1, 2));
    float sm0 = 0.f, sm1 = 0.f;
    #pragma unroll
    for (int ni = 0; ni < 8; ni++) {
        sacc[ni][0] = __expf(sacc[ni][0] - mx0); sm0 += sacc[ni][0];
        sacc[ni][1] = __expf(sacc[ni][1] - mx0); sm0 += sacc[ni][1];
        sacc[ni][2] = __expf(sacc[ni][2] - mx1); sm1 += sacc[ni][2];
        sacc[ni][3] = __expf(sacc[ni][3] - mx1); sm1 += sacc[ni][3];
    }
    sm0 += __shfl_xor_sync(0xffffffffu, sm0, 1);
    sm0 += __shfl_xor_sync(0xffffffffu, sm0, 2);
    sm1 += __shfl_xor_sync(0xffffffffu, sm1, 1);
    sm1 += __shfl_xor_sync(0xffffffffu, sm1, 2);
    float inv0 = 1.f / sm0, inv1 = 1.f / sm1;

    // store P (tf32-converted) back into ps; rows are warp-exclusive -> syncwarp only
    #pragma unroll
    for (int ni = 0; ni < 8; ni++) {
        int c = ni * 8 + 2 * t4;
        float2 p0, p1;
        p0.x = to_tf32_f(sacc[ni][0] * inv0);
        p0.y = to_tf32_f(sacc[ni][1] * inv0);
        p1.x = to_tf32_f(sacc[ni][2] * inv1);
        p1.y = to_tf32_f(sacc[ni][3] * inv1);
        *(float2*)&ps[r0 * 68 + c] = p0;
        *(float2*)&ps[r1 * 68 + c] = p1;
    }
    __syncwarp();

    // ---- O = P V : 8 k-tiles (j) x 4 n-tiles (d) of m16n8k8 ----
    float oacc[4][4];
    #pragma unroll
    for (int ni = 0; ni < 4; ni++)
        #pragma unroll
        for (int r = 0; r < 4; r++) oacc[ni][r] = 0.f;

    #pragma unroll
    for (int kk = 0; kk < 64; kk += 8) {
        uint32_t a[4];
        a[0] = __float_as_uint(ps[(m0 + grp    ) * 68 + kk + t4    ]);
        a[1] = __float_as_uint(ps[(m0 + grp + 8) * 68 + kk + t4    ]);
        a[2] = __float_as_uint(ps[(m0 + grp    ) * 68 + kk + t4 + 4]);
        a[3] = __float_as_uint(ps[(m0 + grp + 8) * 68 + kk + t4 + 4]);
        #pragma unroll
        for (int ni = 0; ni < 4; ni++) {
            uint32_t b[2];
            b[0] = __float_as_uint(vt[(ni * 8 + grp) * 68 + kk + t4    ]);
            b[1] = __float_as_uint(vt[(ni * 8 + grp) * 68 + kk + t4 + 4]);
            mma_tf32(oacc[ni], a, b);
        }
    }

    // ---- write O: row r, col d -> g_ao[(bw*64+r)*512 + hh*32 + d] ----
    int bw = bh >> 4, hh = bh & 15;
    #pragma unroll
    for (int ni = 0; ni < 4; ni++) {
        int d = ni * 8 + 2 * t4;
        size_t base0 = ((size_t)(bw * 64 + r0)) * 512 + hh * 32 + d;
        size_t base1 = ((size_t)(bw * 64 + r1)) * 512 + hh * 32 + d;
        float2 o0, o1;
        o0.x = oacc[ni][0]; o0.y = oacc[ni][1];
        o1.x = oacc[ni][2]; o1.y = oacc[ni][3];
        *(float2*)(g_ao + base0) = o0;
        *(float2*)(g_ao + base1) = o1;
    }
}

// ---------------- launch ----------------
extern "C" void kernel_launch(void* const* d_in, const int* in_sizes, int n_in,
                              void* d_out, int out_size)
{
    const float* x      = (const float*)d_in[0];
    const float* D      = (const float*)d_in[1];
    const float* gamma1 = (const float*)d_in[2];
    const float* beta1  = (const float*)d_in[3];
    const float* Wqkv   = (const float*)d_in[4];
    const float* bqkv   = (const float*)d_in[5];
    const float* Wproj  = (const float*)d_in[6];
    const float* bproj  = (const float*)d_in[7];
    const float* a_p    = (const float*)d_in[8];
    const float* b_p    = (const float*)d_in[9];
    const float* a_r    = (const float*)d_in[10];
    const float* b_r    = (const float*)d_in[11];
    const float* gamma2 = (const float*)d_in[12];
    const float* beta2  = (const float*)d_in[13];
    const float* W1     = (const float*)d_in[14];
    const float* b1     = (const float*)d_in[15];
    const float* W2     = (const float*)d_in[16];
    const float* b2     = (const float*)d_in[17];
    float* out = (float*)d_out;

    float *hwp, *aop, *x2p, *ln2p, *mlpp;
    cudaGetSymbolAddress((void**)&hwp,  g_hw);
    cudaGetSymbolAddress((void**)&aop,  g_ao);
    cudaGetSymbolAddress((void**)&x2p,  g_x2);
    cudaGetSymbolAddress((void**)&ln2p, g_ln2);
    cudaGetSymbolAddress((void**)&mlpp, g_mlp);

    // 1) LN1 + roll(-4,-4) + window partition
    ln_kernel<<<ROWS_, 256>>>(x, gamma1, beta1, hwp, 1);
    // 2) attention bias (A_phi + A_r + mask), all heads
    bias_kernel<<<BW_, 256>>>(D, a_p, b_p, a_r, b_r);
    // 3) QKV GEMM (65536 x 512 x 1536) with split/scatter epilogue
    sgemm_tc<0><<<dim3(12, 512), 256>>>(hwp, Wqkv, bqkv, nullptr, nullptr, 512, 1536);
    // 4) windowed attention (tensor cores)
    attn_tc<<<BW_ * NH_, 128>>>();
    // 5) proj GEMM (65536 x 512 x 512) + window-reverse + roll(+4,+4) + shortcut
    sgemm_tc<1><<<dim3(4, 512), 256>>>(aop, Wproj, bproj, x, nullptr, 512, 512);
    // 6) LN2
    ln_kernel<<<ROWS_, 256>>>(x2p, gamma2, beta2, ln2p, 0);
    // 7) MLP1 (65536 x 512 x 2048) + exact GELU
    sgemm_tc<2><<<dim3(16, 512), 256>>>(ln2p, W1, b1, nullptr, nullptr, 512, 2048);
    // 8) MLP2 (65536 x 2048 x 512) + residual -> d_out
    sgemm_tc<3><<<dim3(4, 512), 256>>>(mlpp, W2, b2, nullptr, out, 2048, 512);
}

// round 14
// speedup vs baseline: 1.0118x; 1.0118x over previous
#include <cuda_runtime.h>
#include <cstdint>
#include <math.h>
#include <math_constants.h>

// ---------------- problem constants ----------------
#define B_    16
#define C_    512
#define NH_   16
#define SS_   4
#define HID_  2048
#define N_    64
#define HD_   32
#define BW_   1024
#define ROWS_ 65536
#define SCALE_ 0.176776695296636893f

// ---------------- scratch (static device memory; no allocations) ----------------
__device__ float g_hw [(size_t)ROWS_ * C_];
__device__ float g_q  [(size_t)BW_ * NH_ * N_ * HD_];
__device__ float g_k  [(size_t)BW_ * NH_ * N_ * HD_];
__device__ float g_v  [(size_t)BW_ * NH_ * N_ * HD_];
__device__ float g_bias[(size_t)BW_ * NH_ * N_ * N_];
__device__ float g_ao [(size_t)ROWS_ * C_];
__device__ float g_x2 [(size_t)ROWS_ * C_];
__device__ float g_ln2[(size_t)ROWS_ * C_];
__device__ float g_mlp[(size_t)ROWS_ * HID_];

// ---------------- helpers ----------------
__device__ __forceinline__ uint32_t to_tf32_u(float x) {
    uint32_t u; asm("cvt.rna.tf32.f32 %0, %1;" : "=r"(u) : "f"(x)); return u;
}
__device__ __forceinline__ float to_tf32_f(float x) { return __uint_as_float(to_tf32_u(x)); }

// pack two fp32 -> f16x2 reg, lo = first (even-k) element
__device__ __forceinline__ uint32_t pk(float lo, float hi) {
    uint32_t r; asm("cvt.rn.f16x2.f32 %0, %1, %2;" : "=r"(r) : "f"(hi), "f"(lo)); return r;
}

__device__ __forceinline__ void mma_tf32(float* c, const uint32_t* a, const uint32_t* b) {
    asm volatile("mma.sync.aligned.m16n8k8.row.col.f32.tf32.tf32.f32 "
        "{%0,%1,%2,%3}, {%4,%5,%6,%7}, {%8,%9}, {%0,%1,%2,%3};\n"
        : "+f"(c[0]), "+f"(c[1]), "+f"(c[2]), "+f"(c[3])
        : "r"(a[0]), "r"(a[1]), "r"(a[2]), "r"(a[3]), "r"(b[0]), "r"(b[1]));
}
__device__ __forceinline__ void mma_f16(float* c, const uint32_t* a, const uint32_t* b) {
    asm volatile("mma.sync.aligned.m16n8k16.row.col.f32.f16.f16.f32 "
        "{%0,%1,%2,%3}, {%4,%5,%6,%7}, {%8,%9}, {%0,%1,%2,%3};\n"
        : "+f"(c[0]), "+f"(c[1]), "+f"(c[2]), "+f"(c[3])
        : "r"(a[0]), "r"(a[1]), "r"(a[2]), "r"(a[3]), "r"(b[0]), "r"(b[1]));
}
__device__ __forceinline__ void cp16(void* smem, const void* gmem) {
    uint32_t s = (uint32_t)__cvta_generic_to_shared(smem);
    asm volatile("cp.async.cg.shared.global [%0], [%1], 16;\n" :: "r"(s), "l"(gmem));
}

// ---------------- LayerNorm (optionally fused with roll + window partition) ----------------
__global__ __launch_bounds__(256) void ln_kernel(
    const float* __restrict__ x, const float* __restrict__ gamma,
    const float* __restrict__ beta, float* __restrict__ out, int win_map)
{
    int row = blockIdx.x;
    int src = row;
    if (win_map) {
        int b = row >> 12, win = (row >> 6) & 63, n = row & 63;
        int hh = (((win >> 3) << 3) + (n >> 3) + SS_) & 63;
        int ww = (((win & 7) << 3) + (n & 7) + SS_) & 63;
        src = (b << 12) + (hh << 6) + ww;
    }
    int t = threadIdx.x;
    float2 v = ((const float2*)(x + (size_t)src * C_))[t];
    float s = v.x + v.y, sq = v.x * v.x + v.y * v.y;
    #pragma unroll
    for (int o = 16; o > 0; o >>= 1) {
        s += __shfl_xor_sync(0xffffffffu, s, o);
        sq += __shfl_xor_sync(0xffffffffu, sq, o);
    }
    __shared__ float redS[8], redQ[8], mv[2];
    int w = t >> 5, l = t & 31;
    if (l == 0) { redS[w] = s; redQ[w] = sq; }
    __syncthreads();
    if (t == 0) {
        float ts = 0.f, tq = 0.f;
        #pragma unroll
        for (int i = 0; i < 8; i++) { ts += redS[i]; tq += redQ[i]; }
        float mean = ts * (1.f / 512.f);
        float var = tq * (1.f / 512.f) - mean * mean;
        mv[0] = mean; mv[1] = rsqrtf(var + 1e-5f);
    }
    __syncthreads();
    float mean = mv[0], r = mv[1];
    float2 gv = ((const float2*)gamma)[t];
    float2 bv = ((const float2*)beta)[t];
    float2 o2;
    o2.x = (v.x - mean) * r * gv.x + bv.x;
    o2.y = (v.y - mean) * r * gv.y + bv.y;
    ((float2*)(out + (size_t)row * C_))[t] = o2;
}

// ---------------- bias kernel ----------------
__global__ __launch_bounds__(256) void bias_kernel(
    const float* __restrict__ D,
    const float* __restrict__ a_p, const float* __restrict__ b_p,
    const float* __restrict__ a_r, const float* __restrict__ b_r)
{
    int bw = blockIdx.x, t = threadIdx.x;
    __shared__ float dws[64];
    __shared__ int regv[64];
    __shared__ float arS[80], brS[64], aphi[240];
    int b = bw >> 6, win = bw & 63, wh = win >> 3, wc = win & 7;
    if (t < 64) {
        int r = t >> 3, sc = t & 7;
        int hh = ((wh << 3) + r + SS_) & 63;
        int wcc = ((wc << 3) + sc + SS_) & 63;
        dws[t] = D[(b << 12) + (hh << 6) + wcc];
        int h0 = (wh << 3) + r, w0 = (wc << 3) + sc;
        int rh = (h0 < 56) ? 0 : (h0 < 60 ? 1 : 2);
        int rw = (w0 < 56) ? 0 : (w0 < 60 ? 1 : 2);
        regv[t] = rh * 3 + rw;
    }
    for (int i = t; i < 80; i += 256) arS[i] = a_r[i];
    for (int i = t; i < 64; i += 256) brS[i] = b_r[i];
    for (int e = t; e < 240; e += 256) {
        int di = e / 16, hdx = e % 16;
        float th = (float)(di - 7) * (2.0f * CUDART_PI_F / 64.0f);
        float c1, s1; sincosf(th, &s1, &c1);
        float cp = c1, sp = s1, cpm = 1.f, spm = 0.f;
        float acc = a_p[hdx];
        #pragma unroll
        for (int p = 0; p < 4; p++) {
            acc += 0.25f * (cp * a_p[(p + 1) * 16 + hdx] + sp * b_p[p * 16 + hdx]);
            float cn = 2.f * c1 * cp - cpm, sn = 2.f * c1 * sp - spm;
            cpm = cp; spm = sp; cp = cn; sp = sn;
        }
        aphi[e] = acc;
    }
    __syncthreads();
    float* bout = g_bias + (size_t)bw * (NH_ * 4096);
    for (int idx = t; idx < 4096; idx += 256) {
        int n = idx >> 6, m = idx & 63;
        float rad = dws[m] - dws[n];
        float c1, s1; sincosf(rad * CUDART_PI_F, &s1, &c1);
        float c2 = 2.f * c1 * c1 - 1.f, s2 = 2.f * c1 * s1;
        float c3 = 2.f * c1 * c2 - c1, s3 = 2.f * c1 * s2 - s1;
        float c4 = 2.f * c1 * c3 - c2, s4 = 2.f * c1 * s3 - s2;
        float mk = (regv[n] == regv[m]) ? 0.f : -100.f;
        const float* ap = &aphi[((n & 7) - (m & 7) + 7) * 16];
        #pragma unroll
        for (int h = 0; h < 16; h++) {
            bout[h * 4096 + idx] = ap[h] + arS[h]
                + 0.25f * (c1 * arS[16 + h] + c2 * arS[32 + h] + c3 * arS[48 + h] + c4 * arS[64 + h]
                         + s1 * brS[h] + s2 * brS[16 + h] + s3 * brS[32 + h] + s4 * brS[48 + h]) + mk;
        }
    }
}

// ---------------- fp16 tensor-core GEMM, 128x128 block, 2-stage cp.async ----------------
// A staged fp32 [m][k] stride 20, B staged fp32 [k][n] stride 132; fp16 pack at
// fragment load (fp16 mantissa == tf32 mantissa, so precision class unchanged).
// m16n8k16: one MMA step per 16-k tile (half the MMA count of tf32 k8).
#define APAD 20
#define BPAD 132
template<int EPI>
__global__ __launch_bounds__(256, 2) void sgemm_tc(
    const float* __restrict__ A, const float* __restrict__ Bw,
    const float* __restrict__ bias, const float* __restrict__ resid,
    float* __restrict__ out, int K, int Nn)
{
    __shared__ float As[2][128][APAD];
    __shared__ float Bs[2][16][BPAD];
    int bx = blockIdx.x, by = blockIdx.y;
    int t  = threadIdx.x;
    int warp = t >> 5, lane = t & 31;
    int wm = warp >> 2, wn = warp & 3;
    int m0 = wm * 64, n0 = wn * 32;
    int grp = lane >> 2, t4 = lane & 3;

    float acc[4][4][4];
    #pragma unroll
    for (int i = 0; i < 4; i++)
        #pragma unroll
        for (int j = 0; j < 4; j++)
            #pragma unroll
            for (int r = 0; r < 4; r++) acc[i][j][r] = 0.f;

    const float* Ap = A + (size_t)(by * 128) * K;
    const float* Bp = Bw + bx * 128;

    auto issue = [&](int stage, int k0) {
        #pragma unroll
        for (int i = 0; i < 2; i++) {
            int c2 = t + i * 256;
            int ar = c2 >> 2, ak = (c2 & 3) << 2;
            cp16(&As[stage][ar][ak], Ap + (size_t)ar * K + k0 + ak);
            int br = c2 >> 5, bc = (c2 & 31) << 2;
            cp16(&Bs[stage][br][bc], Bp + (size_t)(k0 + br) * Nn + bc);
        }
        asm volatile("cp.async.commit_group;\n");
    };

    int ntiles = K >> 4;
    issue(0, 0);
    for (int it = 0; it < ntiles; it++) {
        int s = it & 1;
        if (it + 1 < ntiles) issue(s ^ 1, (it + 1) << 4);
        asm volatile("cp.async.wait_group 1;\n");
        __syncthreads();
        {
            uint32_t af[4][4], bf[4][2];
            int kc = 2 * t4;
            #pragma unroll
            for (int mi = 0; mi < 4; mi++) {
                int mr = m0 + mi * 16;
                float2 p0 = *(const float2*)&As[s][mr + grp    ][kc    ];
                float2 p1 = *(const float2*)&As[s][mr + grp + 8][kc    ];
                float2 p2 = *(const float2*)&As[s][mr + grp    ][kc + 8];
                float2 p3 = *(const float2*)&As[s][mr + grp + 8][kc + 8];
                af[mi][0] = pk(p0.x, p0.y);
                af[mi][1] = pk(p1.x, p1.y);
                af[mi][2] = pk(p2.x, p2.y);
                af[mi][3] = pk(p3.x, p3.y);
            }
            #pragma unroll
            for (int ni = 0; ni < 4; ni++) {
                int nc = n0 + ni * 8;
                bf[ni][0] = pk(Bs[s][kc    ][nc + grp], Bs[s][kc + 1][nc + grp]);
                bf[ni][1] = pk(Bs[s][kc + 8][nc + grp], Bs[s][kc + 9][nc + grp]);
            }
            #pragma unroll
            for (int mi = 0; mi < 4; mi++)
                #pragma unroll
                for (int ni = 0; ni < 4; ni++)
                    mma_f16(acc[mi][ni], af[mi], bf[ni]);
        }
        __syncthreads();
    }

    int rb = by * 128 + m0;
    int cb = bx * 128 + n0;

    #pragma unroll
    for (int mi = 0; mi < 4; mi++) {
        int r0 = rb + mi * 16 + grp;
        #pragma unroll
        for (int ni = 0; ni < 4; ni++) {
            int c = cb + ni * 8 + 2 * t4;
            float2 bb = *(const float2*)(bias + c);
            float v00 = acc[mi][ni][0] + bb.x;
            float v01 = acc[mi][ni][1] + bb.y;
            float v10 = acc[mi][ni][2] + bb.x;
            float v11 = acc[mi][ni][3] + bb.y;

            if (EPI == 0) {
                int s  = c >> 9;
                int hh = (c >> 5) & 15;
                int db = c & 31;
                float* dst = (s == 0) ? g_q : (s == 1 ? g_k : g_v);
                float mul = (s == 0) ? SCALE_ : 1.f;
                #pragma unroll
                for (int h = 0; h < 2; h++) {
                    int row = r0 + h * 8;
                    int bw = row >> 6, n = row & 63;
                    size_t off = ((size_t)(bw * 16 + hh)) * 2048 + n * 32 + db;
                    float2 o2;
                    o2.x = (h ? v10 : v00) * mul;
                    o2.y = (h ? v11 : v01) * mul;
                    *(float2*)(dst + off) = o2;
                }
            } else if (EPI == 1) {
                #pragma unroll
                for (int h = 0; h < 2; h++) {
                    int row = r0 + h * 8;
                    int b = row >> 12, win = (row >> 6) & 63, n = row & 63;
                    int hh = (((win >> 3) << 3) + (n >> 3) + SS_) & 63;
                    int wc = (((win & 7) << 3) + (n & 7) + SS_) & 63;
                    size_t dest = ((size_t)((b << 12) + (hh << 6) + wc)) * 512 + c;
                    float2 rs = *(const float2*)(resid + dest);
                    float2 o2;
                    o2.x = rs.x + (h ? v10 : v00);
                    o2.y = rs.y + (h ? v11 : v01);
                    *(float2*)(g_x2 + dest) = o2;
                }
            } else if (EPI == 2) {
                #pragma unroll
                for (int h = 0; h < 2; h++) {
                    int row = r0 + h * 8;
                    size_t o = (size_t)row * Nn + c;
                    float a0 = h ? v10 : v00;
                    float a1 = h ? v11 : v01;
                    float2 o2;
                    o2.x = 0.5f * a0 * (1.f + erff(a0 * 0.70710678118654752f));
                    o2.y = 0.5f * a1 * (1.f + erff(a1 * 0.70710678118654752f));
                    *(float2*)(g_mlp + o) = o2;
                }
            } else {
                #pragma unroll
                for (int h = 0; h < 2; h++) {
                    int row = r0 + h * 8;
                    size_t o = (size_t)row * 512 + c;
                    float2 rs = *(const float2*)(g_x2 + o);
                    float2 o2;
                    o2.x = rs.x + (h ? v10 : v00);
                    o2.y = rs.y + (h ? v11 : v01);
                    *(float2*)(out + o) = o2;
                }
            }
        }
    }
}

// ---------------- attention via tensor cores (round-8, passing) ----------------
__global__ __launch_bounds__(128) void attn_tc()
{
    int bh = blockIdx.x, t = threadIdx.x;
    int warp = t >> 5, lane = t & 31;
    int grp = lane >> 2, t4 = lane & 3;
    int m0 = warp * 16;
    __shared__ float qs[64 * 36], ks[64 * 36], vt[32 * 68], ps[64 * 68];

    const float4* qg = (const float4*)(g_q + (size_t)bh * 2048);
    const float4* kg = (const float4*)(g_k + (size_t)bh * 2048);
    const float4* vg = (const float4*)(g_v + (size_t)bh * 2048);
    for (int i = t; i < 512; i += 128) {
        int n = i >> 3, kk = (i & 7) << 2;
        float4 qv = qg[i], kv = kg[i], cq, ck;
        cq.x = to_tf32_f(qv.x); cq.y = to_tf32_f(qv.y); cq.z = to_tf32_f(qv.z); cq.w = to_tf32_f(qv.w);
        ck.x = to_tf32_f(kv.x); ck.y = to_tf32_f(kv.y); ck.z = to_tf32_f(kv.z); ck.w = to_tf32_f(kv.w);
        *(float4*)&qs[n * 36 + kk] = cq;
        *(float4*)&ks[n * 36 + kk] = ck;
        float4 vv = vg[i];
        vt[(kk + 0) * 68 + n] = to_tf32_f(vv.x);
        vt[(kk + 1) * 68 + n] = to_tf32_f(vv.y);
        vt[(kk + 2) * 68 + n] = to_tf32_f(vv.z);
        vt[(kk + 3) * 68 + n] = to_tf32_f(vv.w);
    }
    const float4* bgp = (const float4*)(g_bias + (size_t)bh * 4096);
    for (int i = t; i < 1024; i += 128) {
        int n = i >> 4, c4 = (i & 15) << 2;
        *(float4*)&ps[n * 68 + c4] = bgp[i];
    }
    __syncthreads();

    float sacc[8][4];
    #pragma unroll
    for (int ni = 0; ni < 8; ni++)
        #pragma unroll
        for (int r = 0; r < 4; r++) sacc[ni][r] = 0.f;
    #pragma unroll
    for (int kk = 0; kk < 32; kk += 8) {
        uint32_t a[4];
        a[0] = __float_as_uint(qs[(m0 + grp    ) * 36 + kk + t4    ]);
        a[1] = __float_as_uint(qs[(m0 + grp + 8) * 36 + kk + t4    ]);
        a[2] = __float_as_uint(qs[(m0 + grp    ) * 36 + kk + t4 + 4]);
        a[3] = __float_as_uint(qs[(m0 + grp + 8) * 36 + kk + t4 + 4]);
        #pragma unroll
        for (int ni = 0; ni < 8; ni++) {
            uint32_t b[2];
            b[0] = __float_as_uint(ks[(ni * 8 + grp) * 36 + kk + t4    ]);
            b[1] = __float_as_uint(ks[(ni * 8 + grp) * 36 + kk + t4 + 4]);
            mma_tf32(sacc[ni], a, b);
        }
    }
    int r0 = m0 + grp, r1 = r0 + 8;
    #pragma unroll
    for (int ni = 0; ni < 8; ni++) {
        int c = ni * 8 + 2 * t4;
        float2 b0 = *(const float2*)&ps[r0 * 68 + c];
        float2 b1 = *(const float2*)&ps[r1 * 68 + c];
        sacc[ni][0] += b0.x; sacc[ni][1] += b0.y;
        sacc[ni][2] += b1.x; sacc[ni][3] += b1.y;
    }
    float mx0 = sacc[0][0], mx1 = sacc[0][2];
    #pragma unroll
    for (int ni = 0; ni < 8; ni++) {
        mx0 = fmaxf(mx0, fmaxf(sacc[ni][0], sacc[ni][1]));
        mx1 = fmaxf(mx1, fmaxf(sacc[ni][2], sacc[ni][3]));
    }
    mx0 = fmaxf(mx0, __shfl_xor_sync(0xffffffffu, mx0, 1));
    mx0 = fmaxf(mx0, __shfl_xor_sync(0xffffffffu, mx0, 2));
    mx1 = fmaxf(mx1, __shfl_xor_sync(0xffffffffu, mx1, 1));
    mx1 = fmaxf(mx1, __shfl_xor_sync(0xffffffffu, mx1, 2));
    float sm0 = 0.f, sm1 = 0.f;
    #pragma unroll
    for (int ni = 0; ni < 8; ni++) {
        sacc[ni][0] = __expf(sacc[ni][0] - mx0); sm0 += sacc[ni][0];
        sacc[ni][1] = __expf(sacc[ni][1] - mx0); sm0 += sacc[ni][1];
        sacc[ni][2] = __expf(sacc[ni][2] - mx1); sm1 += sacc[ni][2];
        sacc[ni][3] = __expf(sacc[ni][3] - mx1); sm1 += sacc[ni][3];
    }
    sm0 += __shfl_xor_sync(0xffffffffu, sm0, 1);
    sm0 += __shfl_xor_sync(0xffffffffu, sm0, 2);
    sm1 += __shfl_xor_sync(0xffffffffu, sm1, 1);
    sm1 += __shfl_xor_sync(0xffffffffu, sm1, 2);
    float inv0 = 1.f / sm0, inv1 = 1.f / sm1;
    #pragma unroll
    for (int ni = 0; ni < 8; ni++) {
        int c = ni * 8 + 2 * t4;
        float2 p0, p1;
        p0.x = to_tf32_f(sacc[ni][0] * inv0);
        p0.y = to_tf32_f(sacc[ni][1] * inv0);
        p1.x = to_tf32_f(sacc[ni][2] * inv1);
        p1.y = to_tf32_f(sacc[ni][3] * inv1);
        *(float2*)&ps[r0 * 68 + c] = p0;
        *(float2*)&ps[r1 * 68 + c] = p1;
    }
    __syncwarp();

    float oacc[4][4];
    #pragma unroll
    for (int ni = 0; ni < 4; ni++)
        #pragma unroll
        for (int r = 0; r < 4; r++) oacc[ni][r] = 0.f;
    #pragma unroll
    for (int kk = 0; kk < 64; kk += 8) {
        uint32_t a[4];
        a[0] = __float_as_uint(ps[(m0 + grp    ) * 68 + kk + t4    ]);
        a[1] = __float_as_uint(ps[(m0 + grp + 8) * 68 + kk + t4    ]);
        a[2] = __float_as_uint(ps[(m0 + grp    ) * 68 + kk + t4 + 4]);
        a[3] = __float_as_uint(ps[(m0 + grp + 8) * 68 + kk + t4 + 4]);
        #pragma unroll
        for (int ni = 0; ni < 4; ni++) {
            uint32_t b[2];
            b[0] = __float_as_uint(vt[(ni * 8 + grp) * 68 + kk + t4    ]);
            b[1] = __float_as_uint(vt[(ni * 8 + grp) * 68 + kk + t4 + 4]);
            mma_tf32(oacc[ni], a, b);
        }
    }
    int bw = bh >> 4, hh = bh & 15;
    #pragma unroll
    for (int ni = 0; ni < 4; ni++) {
        int d = ni * 8 + 2 * t4;
        size_t b0 = ((size_t)(bw * 64 + r0)) * 512 + hh * 32 + d;
        size_t b1 = ((size_t)(bw * 64 + r1)) * 512 + hh * 32 + d;
        float2 o0, o1;
        o0.x = oacc[ni][0]; o0.y = oacc[ni][1];
        o1.x = oacc[ni][2]; o1.y = oacc[ni][3];
        *(float2*)(g_ao + b0) = o0;
        *(float2*)(g_ao + b1) = o1;
    }
}

// ---------------- launch ----------------
extern "C" void kernel_launch(void* const* d_in, const int* in_sizes, int n_in,
                              void* d_out, int out_size)
{
    const float* x      = (const float*)d_in[0];
    const float* D      = (const float*)d_in[1];
    const float* gamma1 = (const float*)d_in[2];
    const float* beta1  = (const float*)d_in[3];
    const float* Wqkv   = (const float*)d_in[4];
    const float* bqkv   = (const float*)d_in[5];
    const float* Wproj  = (const float*)d_in[6];
    const float* bproj  = (const float*)d_in[7];
    const float* a_p    = (const float*)d_in[8];
    const float* b_p    = (const float*)d_in[9];
    const float* a_r    = (const float*)d_in[10];
    const float* b_r    = (const float*)d_in[11];
    const float* gamma2 = (const float*)d_in[12];
    const float* beta2  = (const float*)d_in[13];
    const float* W1     = (const float*)d_in[14];
    const float* b1     = (const float*)d_in[15];
    const float* W2     = (const float*)d_in[16];
    const float* b2     = (const float*)d_in[17];
    float* out = (float*)d_out;

    float *hwp, *aop, *x2p, *ln2p, *mlpp;
    cudaGetSymbolAddress((void**)&hwp,  g_hw);
    cudaGetSymbolAddress((void**)&aop,  g_ao);
    cudaGetSymbolAddress((void**)&x2p,  g_x2);
    cudaGetSymbolAddress((void**)&ln2p, g_ln2);
    cudaGetSymbolAddress((void**)&mlpp, g_mlp);

    ln_kernel<<<ROWS_, 256>>>(x, gamma1, beta1, hwp, 1);
    bias_kernel<<<BW_, 256>>>(D, a_p, b_p, a_r, b_r);
    sgemm_tc<0><<<dim3(12, 512), 256>>>(hwp, Wqkv, bqkv, nullptr, nullptr, 512, 1536);
    attn_tc<<<BW_ * NH_, 128>>>();
    sgemm_tc<1><<<dim3(4, 512), 256>>>(aop, Wproj, bproj, x, nullptr, 512, 512);
    ln_kernel<<<ROWS_, 256>>>(x2p, gamma2, beta2, ln2p, 0);
    sgemm_tc<2><<<dim3(16, 512), 256>>>(ln2p, W1, b1, nullptr, nullptr, 512, 2048);
    sgemm_tc<3><<<dim3(4, 512), 256>>>(mlpp, W2, b2, nullptr, out, 2048, 512);
}

// round 16
// speedup vs baseline: 1.4122x; 1.3957x over previous
#include <cuda_runtime.h>
#include <cuda_fp16.h>
#include <cstdint>
#include <math.h>
#include <math_constants.h>

// ---------------- problem constants ----------------
#define B_    16
#define C_    512
#define NH_   16
#define SS_   4
#define HID_  2048
#define N_    64
#define HD_   32
#define BW_   1024
#define ROWS_ 65536
#define SCALE_ 0.176776695296636893f

// ---------------- scratch (static device memory; no allocations) ----------------
__device__ __align__(128) __half g_hw [(size_t)ROWS_ * C_];    // LN1 out (fp16, windowed)
__device__ __align__(128) float  g_q  [(size_t)BW_ * NH_ * N_ * HD_];
__device__ __align__(128) float  g_k  [(size_t)BW_ * NH_ * N_ * HD_];
__device__ __align__(128) float  g_v  [(size_t)BW_ * NH_ * N_ * HD_];
__device__ __align__(128) float  g_bias[(size_t)BW_ * NH_ * N_ * N_];
__device__ __align__(128) __half g_ao [(size_t)ROWS_ * C_];    // attn out (fp16, windowed)
__device__ __align__(128) float  g_x2 [(size_t)ROWS_ * C_];    // residual trunk (fp32)
__device__ __align__(128) __half g_ln2[(size_t)ROWS_ * C_];    // LN2 out (fp16)
__device__ __align__(128) __half g_mlp[(size_t)ROWS_ * HID_];  // GELU out (fp16)
__device__ __align__(128) __half g_wt [3145728];               // fp16 weights, [N][K]
#define WT_QKV  0
#define WT_PROJ 786432
#define WT_W1   1048576
#define WT_W2   2097152

// ---------------- helpers ----------------
__device__ __forceinline__ uint32_t to_tf32_u(float x) {
    uint32_t u; asm("cvt.rna.tf32.f32 %0, %1;" : "=r"(u) : "f"(x)); return u;
}
__device__ __forceinline__ float to_tf32_f(float x) { return __uint_as_float(to_tf32_u(x)); }

__device__ __forceinline__ void mma_tf32(float* c, const uint32_t* a, const uint32_t* b) {
    asm volatile("mma.sync.aligned.m16n8k8.row.col.f32.tf32.tf32.f32 "
        "{%0,%1,%2,%3}, {%4,%5,%6,%7}, {%8,%9}, {%0,%1,%2,%3};\n"
        : "+f"(c[0]), "+f"(c[1]), "+f"(c[2]), "+f"(c[3])
        : "r"(a[0]), "r"(a[1]), "r"(a[2]), "r"(a[3]), "r"(b[0]), "r"(b[1]));
}
__device__ __forceinline__ void mma_f16(float* c, const uint32_t* a, const uint32_t* b) {
    asm volatile("mma.sync.aligned.m16n8k16.row.col.f32.f16.f16.f32 "
        "{%0,%1,%2,%3}, {%4,%5,%6,%7}, {%8,%9}, {%0,%1,%2,%3};\n"
        : "+f"(c[0]), "+f"(c[1]), "+f"(c[2]), "+f"(c[3])
        : "r"(a[0]), "r"(a[1]), "r"(a[2]), "r"(a[3]), "r"(b[0]), "r"(b[1]));
}
__device__ __forceinline__ void cp16(void* smem, const void* gmem) {
    uint32_t s = (uint32_t)__cvta_generic_to_shared(smem);
    asm volatile("cp.async.cg.shared.global [%0], [%1], 16;\n" :: "r"(s), "l"(gmem));
}

// ---------------- LayerNorm -> fp16 out (optionally fused roll + window partition) ----------------
__global__ __launch_bounds__(256) void ln_kernel(
    const float* __restrict__ x, const float* __restrict__ gamma,
    const float* __restrict__ beta, __half* __restrict__ out, int win_map)
{
    int row = blockIdx.x;
    int src = row;
    if (win_map) {
        int b = row >> 12, win = (row >> 6) & 63, n = row & 63;
        int hh = (((win >> 3) << 3) + (n >> 3) + SS_) & 63;
        int ww = (((win & 7) << 3) + (n & 7) + SS_) & 63;
        src = (b << 12) + (hh << 6) + ww;
    }
    int t = threadIdx.x;
    float2 v = ((const float2*)(x + (size_t)src * C_))[t];
    float s = v.x + v.y, sq = v.x * v.x + v.y * v.y;
    #pragma unroll
    for (int o = 16; o > 0; o >>= 1) {
        s += __shfl_xor_sync(0xffffffffu, s, o);
        sq += __shfl_xor_sync(0xffffffffu, sq, o);
    }
    __shared__ float redS[8], redQ[8], mv[2];
    int w = t >> 5, l = t & 31;
    if (l == 0) { redS[w] = s; redQ[w] = sq; }
    __syncthreads();
    if (t == 0) {
        float ts = 0.f, tq = 0.f;
        #pragma unroll
        for (int i = 0; i < 8; i++) { ts += redS[i]; tq += redQ[i]; }
        float mean = ts * (1.f / 512.f);
        float var = tq * (1.f / 512.f) - mean * mean;
        mv[0] = mean; mv[1] = rsqrtf(var + 1e-5f);
    }
    __syncthreads();
    float mean = mv[0], r = mv[1];
    float2 gv = ((const float2*)gamma)[t];
    float2 bv = ((const float2*)beta)[t];
    float ox = (v.x - mean) * r * gv.x + bv.x;
    float oy = (v.y - mean) * r * gv.y + bv.y;
    ((__half2*)(out + (size_t)row * C_))[t] = __floats2half2_rn(ox, oy);
}

// ---------------- bias kernel ----------------
__global__ __launch_bounds__(256) void bias_kernel(
    const float* __restrict__ D,
    const float* __restrict__ a_p, const float* __restrict__ b_p,
    const float* __restrict__ a_r, const float* __restrict__ b_r)
{
    int bw = blockIdx.x, t = threadIdx.x;
    __shared__ float dws[64];
    __shared__ int regv[64];
    __shared__ float arS[80], brS[64], aphi[240];
    int b = bw >> 6, win = bw & 63, wh = win >> 3, wc = win & 7;
    if (t < 64) {
        int r = t >> 3, sc = t & 7;
        int hh = ((wh << 3) + r + SS_) & 63;
        int wcc = ((wc << 3) + sc + SS_) & 63;
        dws[t] = D[(b << 12) + (hh << 6) + wcc];
        int h0 = (wh << 3) + r, w0 = (wc << 3) + sc;
        int rh = (h0 < 56) ? 0 : (h0 < 60 ? 1 : 2);
        int rw = (w0 < 56) ? 0 : (w0 < 60 ? 1 : 2);
        regv[t] = rh * 3 + rw;
    }
    for (int i = t; i < 80; i += 256) arS[i] = a_r[i];
    for (int i = t; i < 64; i += 256) brS[i] = b_r[i];
    for (int e = t; e < 240; e += 256) {
        int di = e / 16, hdx = e % 16;
        float th = (float)(di - 7) * (2.0f * CUDART_PI_F / 64.0f);
        float c1, s1; sincosf(th, &s1, &c1);
        float cp = c1, sp = s1, cpm = 1.f, spm = 0.f;
        float acc = a_p[hdx];
        #pragma unroll
        for (int p = 0; p < 4; p++) {
            acc += 0.25f * (cp * a_p[(p + 1) * 16 + hdx] + sp * b_p[p * 16 + hdx]);
            float cn = 2.f * c1 * cp - cpm, sn = 2.f * c1 * sp - spm;
            cpm = cp; spm = sp; cp = cn; sp = sn;
        }
        aphi[e] = acc;
    }
    __syncthreads();
    float* bout = g_bias + (size_t)bw * (NH_ * 4096);
    for (int idx = t; idx < 4096; idx += 256) {
        int n = idx >> 6, m = idx & 63;
        float rad = dws[m] - dws[n];
        float c1, s1; sincosf(rad * CUDART_PI_F, &s1, &c1);
        float c2 = 2.f * c1 * c1 - 1.f, s2 = 2.f * c1 * s1;
        float c3 = 2.f * c1 * c2 - c1, s3 = 2.f * c1 * s2 - s1;
        float c4 = 2.f * c1 * c3 - c2, s4 = 2.f * c1 * s3 - s2;
        float mk = (regv[n] == regv[m]) ? 0.f : -100.f;
        const float* ap = &aphi[((n & 7) - (m & 7) + 7) * 16];
        #pragma unroll
        for (int h = 0; h < 16; h++) {
            bout[h * 4096 + idx] = ap[h] + arS[h]
                + 0.25f * (c1 * arS[16 + h] + c2 * arS[32 + h] + c3 * arS[48 + h] + c4 * arS[64 + h]
                         + s1 * brS[h] + s2 * brS[16 + h] + s3 * brS[32 + h] + s4 * brS[48 + h]) + mk;
        }
    }
}

// ---------------- weight convert+transpose: fp32 [R][C] -> fp16 [C][R] ----------------
__global__ __launch_bounds__(256) void wcvt(
    const float* __restrict__ in, __half* __restrict__ outp, int R, int Cc)
{
    __shared__ float tile[32][33];
    int c0 = blockIdx.x * 32, r0 = blockIdx.y * 32;
    int tx = threadIdx.x & 31, ty = threadIdx.x >> 5;
    #pragma unroll
    for (int i = ty; i < 32; i += 8) tile[i][tx] = in[(size_t)(r0 + i) * Cc + c0 + tx];
    __syncthreads();
    #pragma unroll
    for (int i = ty; i < 32; i += 8)
        outp[(size_t)(c0 + i) * R + r0 + tx] = __float2half(tile[tx][i]);
}

// ---------------- fp16 GEMM: A fp16 [M][K], B fp16 [N][K], 128x128, 2-stage cp.async ----------------
// smem rows: 8 u32 k-pairs, row stride 12 u32 (48 B: 16B-aligned for cp.async,
// and 12*grp+t4 mod 32 covers all banks -> conflict-free). No cvt in mainloop.
template<int EPI>
__global__ __launch_bounds__(256, 2) void sgemm_h(
    const __half* __restrict__ A, const __half* __restrict__ Bt,
    const float* __restrict__ bias, const float* __restrict__ resid,
    float* __restrict__ out, int K, int Nn)
{
    __shared__ uint32_t As[2][128][12];
    __shared__ uint32_t Bs[2][128][12];
    int bx = blockIdx.x, by = blockIdx.y;
    int t  = threadIdx.x;
    int warp = t >> 5, lane = t & 31;
    int wm = warp >> 2, wn = warp & 3;
    int m0 = wm * 64, n0 = wn * 32;
    int grp = lane >> 2, t4 = lane & 3;

    float acc[4][4][4];
    #pragma unroll
    for (int i = 0; i < 4; i++)
        #pragma unroll
        for (int j = 0; j < 4; j++)
            #pragma unroll
            for (int r = 0; r < 4; r++) acc[i][j][r] = 0.f;

    const __half* Ap = A + (size_t)(by * 128) * K;
    const __half* Bp = Bt + (size_t)(bx * 128) * K;

    // per tile: A 256 16B-chunks (128 rows x 2), B 256 chunks; 1 each per thread
    int rowA = t >> 1, hsel = t & 1;
    auto issue = [&](int stage, int k0) {
        cp16(&As[stage][rowA][hsel * 4], Ap + (size_t)rowA * K + k0 + hsel * 8);
        cp16(&Bs[stage][rowA][hsel * 4], Bp + (size_t)rowA * K + k0 + hsel * 8);
        asm volatile("cp.async.commit_group;\n");
    };

    int ntiles = K >> 4;
    issue(0, 0);
    for (int it = 0; it < ntiles; it++) {
        int s = it & 1;
        if (it + 1 < ntiles) issue(s ^ 1, (it + 1) << 4);
        asm volatile("cp.async.wait_group 1;\n");
        __syncthreads();
        {
            uint32_t af[4][4], bf[4][2];
            #pragma unroll
            for (int mi = 0; mi < 4; mi++) {
                int mr = m0 + mi * 16;
                af[mi][0] = As[s][mr + grp    ][t4    ];
                af[mi][1] = As[s][mr + grp + 8][t4    ];
                af[mi][2] = As[s][mr + grp    ][t4 + 4];
                af[mi][3] = As[s][mr + grp + 8][t4 + 4];
            }
            #pragma unroll
            for (int ni = 0; ni < 4; ni++) {
                int nc = n0 + ni * 8;
                bf[ni][0] = Bs[s][nc + grp][t4    ];
                bf[ni][1] = Bs[s][nc + grp][t4 + 4];
            }
            #pragma unroll
            for (int mi = 0; mi < 4; mi++)
                #pragma unroll
                for (int ni = 0; ni < 4; ni++)
                    mma_f16(acc[mi][ni], af[mi], bf[ni]);
        }
        __syncthreads();
    }

    int rb = by * 128 + m0;
    int cb = bx * 128 + n0;

    #pragma unroll
    for (int mi = 0; mi < 4; mi++) {
        int r0 = rb + mi * 16 + grp;
        #pragma unroll
        for (int ni = 0; ni < 4; ni++) {
            int c = cb + ni * 8 + 2 * t4;
            float2 bb = *(const float2*)(bias + c);
            float v00 = acc[mi][ni][0] + bb.x;
            float v01 = acc[mi][ni][1] + bb.y;
            float v10 = acc[mi][ni][2] + bb.x;
            float v11 = acc[mi][ni][3] + bb.y;

            if (EPI == 0) {            // QKV scatter (fp32 out for attn)
                int s2 = c >> 9;
                int hh = (c >> 5) & 15;
                int db = c & 31;
                float* dst = (s2 == 0) ? g_q : (s2 == 1 ? g_k : g_v);
                float mul = (s2 == 0) ? SCALE_ : 1.f;
                #pragma unroll
                for (int h = 0; h < 2; h++) {
                    int row = r0 + h * 8;
                    int bw = row >> 6, n = row & 63;
                    size_t off = ((size_t)(bw * 16 + hh)) * 2048 + n * 32 + db;
                    float2 o2;
                    o2.x = (h ? v10 : v00) * mul;
                    o2.y = (h ? v11 : v01) * mul;
                    *(float2*)(dst + off) = o2;
                }
            } else if (EPI == 1) {     // proj + window-reverse + roll + shortcut (fp32)
                #pragma unroll
                for (int h = 0; h < 2; h++) {
                    int row = r0 + h * 8;
                    int b = row >> 12, win = (row >> 6) & 63, n = row & 63;
                    int hh = (((win >> 3) << 3) + (n >> 3) + SS_) & 63;
                    int wc = (((win & 7) << 3) + (n & 7) + SS_) & 63;
                    size_t dest = ((size_t)((b << 12) + (hh << 6) + wc)) * 512 + c;
                    float2 rs = *(const float2*)(resid + dest);
                    float2 o2;
                    o2.x = rs.x + (h ? v10 : v00);
                    o2.y = rs.y + (h ? v11 : v01);
                    *(float2*)(g_x2 + dest) = o2;
                }
            } else if (EPI == 2) {     // MLP1 + exact GELU -> fp16
                #pragma unroll
                for (int h = 0; h < 2; h++) {
                    int row = r0 + h * 8;
                    size_t o = (size_t)row * Nn + c;
                    float a0 = h ? v10 : v00;
                    float a1 = h ? v11 : v01;
                    float gx = 0.5f * a0 * (1.f + erff(a0 * 0.70710678118654752f));
                    float gy = 0.5f * a1 * (1.f + erff(a1 * 0.70710678118654752f));
                    *(__half2*)(g_mlp + o) = __floats2half2_rn(gx, gy);
                }
            } else {                   // MLP2 + residual -> out (fp32)
                #pragma unroll
                for (int h = 0; h < 2; h++) {
                    int row = r0 + h * 8;
                    size_t o = (size_t)row * 512 + c;
                    float2 rs = *(const float2*)(g_x2 + o);
                    float2 o2;
                    o2.x = rs.x + (h ? v10 : v00);
                    o2.y = rs.y + (h ? v11 : v01);
                    *(float2*)(out + o) = o2;
                }
            }
        }
    }
}

// ---------------- attention via tensor cores (round-8 core; fp16 output) ----------------
__global__ __launch_bounds__(128) void attn_tc()
{
    int bh = blockIdx.x, t = threadIdx.x;
    int warp = t >> 5, lane = t & 31;
    int grp = lane >> 2, t4 = lane & 3;
    int m0 = warp * 16;
    __shared__ float qs[64 * 36], ks[64 * 36], vt[32 * 68], ps[64 * 68];

    const float4* qg = (const float4*)(g_q + (size_t)bh * 2048);
    const float4* kg = (const float4*)(g_k + (size_t)bh * 2048);
    const float4* vg = (const float4*)(g_v + (size_t)bh * 2048);
    for (int i = t; i < 512; i += 128) {
        int n = i >> 3, kk = (i & 7) << 2;
        float4 qv = qg[i], kv = kg[i], cq, ck;
        cq.x = to_tf32_f(qv.x); cq.y = to_tf32_f(qv.y); cq.z = to_tf32_f(qv.z); cq.w = to_tf32_f(qv.w);
        ck.x = to_tf32_f(kv.x); ck.y = to_tf32_f(kv.y); ck.z = to_tf32_f(kv.z); ck.w = to_tf32_f(kv.w);
        *(float4*)&qs[n * 36 + kk] = cq;
        *(float4*)&ks[n * 36 + kk] = ck;
        float4 vv = vg[i];
        vt[(kk + 0) * 68 + n] = to_tf32_f(vv.x);
        vt[(kk + 1) * 68 + n] = to_tf32_f(vv.y);
        vt[(kk + 2) * 68 + n] = to_tf32_f(vv.z);
        vt[(kk + 3) * 68 + n] = to_tf32_f(vv.w);
    }
    const float4* bgp = (const float4*)(g_bias + (size_t)bh * 4096);
    for (int i = t; i < 1024; i += 128) {
        int n = i >> 4, c4 = (i & 15) << 2;
        *(float4*)&ps[n * 68 + c4] = bgp[i];
    }
    __syncthreads();

    float sacc[8][4];
    #pragma unroll
    for (int ni = 0; ni < 8; ni++)
        #pragma unroll
        for (int r = 0; r < 4; r++) sacc[ni][r] = 0.f;
    #pragma unroll
    for (int kk = 0; kk < 32; kk += 8) {
        uint32_t a[4];
        a[0] = __float_as_uint(qs[(m0 + grp    ) * 36 + kk + t4    ]);
        a[1] = __float_as_uint(qs[(m0 + grp + 8) * 36 + kk + t4    ]);
        a[2] = __float_as_uint(qs[(m0 + grp    ) * 36 + kk + t4 + 4]);
        a[3] = __float_as_uint(qs[(m0 + grp + 8) * 36 + kk + t4 + 4]);
        #pragma unroll
        for (int ni = 0; ni < 8; ni++) {
            uint32_t b[2];
            b[0] = __float_as_uint(ks[(ni * 8 + grp) * 36 + kk + t4    ]);
            b[1] = __float_as_uint(ks[(ni * 8 + grp) * 36 + kk + t4 + 4]);
            mma_tf32(sacc[ni], a, b);
        }
    }
    int r0 = m0 + grp, r1 = r0 + 8;
    #pragma unroll
    for (int ni = 0; ni < 8; ni++) {
        int c = ni * 8 + 2 * t4;
        float2 b0 = *(const float2*)&ps[r0 * 68 + c];
        float2 b1 = *(const float2*)&ps[r1 * 68 + c];
        sacc[ni][0] += b0.x; sacc[ni][1] += b0.y;
        sacc[ni][2] += b1.x; sacc[ni][3] += b1.y;
    }
    float mx0 = sacc[0][0], mx1 = sacc[0][2];
    #pragma unroll
    for (int ni = 0; ni < 8; ni++) {
        mx0 = fmaxf(mx0, fmaxf(sacc[ni][0], sacc[ni][1]));
        mx1 = fmaxf(mx1, fmaxf(sacc[ni][2], sacc[ni][3]));
    }
    mx0 = fmaxf(mx0, __shfl_xor_sync(0xffffffffu, mx0, 1));
    mx0 = fmaxf(mx0, __shfl_xor_sync(0xffffffffu, mx0, 2));
    mx1 = fmaxf(mx1, __shfl_xor_sync(0xffffffffu, mx1, 1));
    mx1 = fmaxf(mx1, __shfl_xor_sync(0xffffffffu, mx1, 2));
    float sm0 = 0.f, sm1 = 0.f;
    #pragma unroll
    for (int ni = 0; ni < 8; ni++) {
        sacc[ni][0] = __expf(sacc[ni][0] - mx0); sm0 += sacc[ni][0];
        sacc[ni][1] = __expf(sacc[ni][1] - mx0); sm0 += sacc[ni][1];
        sacc[ni][2] = __expf(sacc[ni][2] - mx1); sm1 += sacc[ni][2];
        sacc[ni][3] = __expf(sacc[ni][3] - mx1); sm1 += sacc[ni][3];
    }
    sm0 += __shfl_xor_sync(0xffffffffu, sm0, 1);
    sm0 += __shfl_xor_sync(0xffffffffu, sm0, 2);
    sm1 += __shfl_xor_sync(0xffffffffu, sm1, 1);
    sm1 += __shfl_xor_sync(0xffffffffu, sm1, 2);
    float inv0 = 1.f / sm0, inv1 = 1.f / sm1;
    #pragma unroll
    for (int ni = 0; ni < 8; ni++) {
        int c = ni * 8 + 2 * t4;
        float2 p0, p1;
        p0.x = to_tf32_f(sacc[ni][0] * inv0);
        p0.y = to_tf32_f(sacc[ni][1] * inv0);
        p1.x = to_tf32_f(sacc[ni][2] * inv1);
        p1.y = to_tf32_f(sacc[ni][3] * inv1);
        *(float2*)&ps[r0 * 68 + c] = p0;
        *(float2*)&ps[r1 * 68 + c] = p1;
    }
    __syncwarp();

    float oacc[4][4];
    #pragma unroll
    for (int ni = 0; ni < 4; ni++)
        #pragma unroll
        for (int r = 0; r < 4; r++) oacc[ni][r] = 0.f;
    #pragma unroll
    for (int kk = 0; kk < 64; kk += 8) {
        uint32_t a[4];
        a[0] = __float_as_uint(ps[(m0 + grp    ) * 68 + kk + t4    ]);
        a[1] = __float_as_uint(ps[(m0 + grp + 8) * 68 + kk + t4    ]);
        a[2] = __float_as_uint(ps[(m0 + grp    ) * 68 + kk + t4 + 4]);
        a[3] = __float_as_uint(ps[(m0 + grp + 8) * 68 + kk + t4 + 4]);
        #pragma unroll
        for (int ni = 0; ni < 4; ni++) {
            uint32_t b[2];
            b[0] = __float_as_uint(vt[(ni * 8 + grp) * 68 + kk + t4    ]);
            b[1] = __float_as_uint(vt[(ni * 8 + grp) * 68 + kk + t4 + 4]);
            mma_tf32(oacc[ni], a, b);
        }
    }
    int bw = bh >> 4, hh = bh & 15;
    #pragma unroll
    for (int ni = 0; ni < 4; ni++) {
        int d = ni * 8 + 2 * t4;
        size_t b0 = ((size_t)(bw * 64 + r0)) * 512 + hh * 32 + d;
        size_t b1 = ((size_t)(bw * 64 + r1)) * 512 + hh * 32 + d;
        *(__half2*)(g_ao + b0) = __floats2half2_rn(oacc[ni][0], oacc[ni][1]);
        *(__half2*)(g_ao + b1) = __floats2half2_rn(oacc[ni][2], oacc[ni][3]);
    }
}

// ---------------- launch ----------------
extern "C" void kernel_launch(void* const* d_in, const int* in_sizes, int n_in,
                              void* d_out, int out_size)
{
    const float* x      = (const float*)d_in[0];
    const float* D      = (const float*)d_in[1];
    const float* gamma1 = (const float*)d_in[2];
    const float* beta1  = (const float*)d_in[3];
    const float* Wqkv   = (const float*)d_in[4];
    const float* bqkv   = (const float*)d_in[5];
    const float* Wproj  = (const float*)d_in[6];
    const float* bproj  = (const float*)d_in[7];
    const float* a_p    = (const float*)d_in[8];
    const float* b_p    = (const float*)d_in[9];
    const float* a_r    = (const float*)d_in[10];
    const float* b_r    = (const float*)d_in[11];
    const float* gamma2 = (const float*)d_in[12];
    const float* beta2  = (const float*)d_in[13];
    const float* W1     = (const float*)d_in[14];
    const float* b1     = (const float*)d_in[15];
    const float* W2     = (const float*)d_in[16];
    const float* b2     = (const float*)d_in[17];
    float* out = (float*)d_out;

    __half *hwp, *aop, *ln2p, *mlpp, *wtp;
    float *x2p;
    cudaGetSymbolAddress((void**)&hwp,  g_hw);
    cudaGetSymbolAddress((void**)&aop,  g_ao);
    cudaGetSymbolAddress((void**)&x2p,  g_x2);
    cudaGetSymbolAddress((void**)&ln2p, g_ln2);
    cudaGetSymbolAddress((void**)&mlpp, g_mlp);
    cudaGetSymbolAddress((void**)&wtp,  g_wt);

    // weight convert + transpose: fp32 [K][N] -> fp16 [N][K]
    wcvt<<<dim3(48, 16), 256>>>(Wqkv, wtp + WT_QKV, 512, 1536);
    wcvt<<<dim3(16, 16), 256>>>(Wproj, wtp + WT_PROJ, 512, 512);
    wcvt<<<dim3(64, 16), 256>>>(W1, wtp + WT_W1, 512, 2048);
    wcvt<<<dim3(16, 64), 256>>>(W2, wtp + WT_W2, 2048, 512);

    // 1) LN1 + roll + window partition -> fp16
    ln_kernel<<<ROWS_, 256>>>(x, gamma1, beta1, hwp, 1);
    // 2) attention bias
    bias_kernel<<<BW_, 256>>>(D, a_p, b_p, a_r, b_r);
    // 3) QKV GEMM (fp16 in, fp32 scatter out)
    sgemm_h<0><<<dim3(12, 512), 256>>>(hwp, wtp + WT_QKV, bqkv, nullptr, nullptr, 512, 1536);
    // 4) windowed attention -> fp16 g_ao
    attn_tc<<<BW_ * NH_, 128>>>();
    // 5) proj GEMM + window-reverse + roll + shortcut -> fp32 g_x2
    sgemm_h<1><<<dim3(4, 512), 256>>>(aop, wtp + WT_PROJ, bproj, x, nullptr, 512, 512);
    // 6) LN2 -> fp16
    ln_kernel<<<ROWS_, 256>>>(x2p, gamma2, beta2, ln2p, 0);
    // 7) MLP1 + GELU -> fp16 g_mlp
    sgemm_h<2><<<dim3(16, 512), 256>>>(ln2p, wtp + WT_W1, b1, nullptr, nullptr, 512, 2048);
    // 8) MLP2 + residual -> fp32 out
    sgemm_h<3><<<dim3(4, 512), 256>>>(mlpp, wtp + WT_W2, b2, nullptr, out, 2048, 512);
}